// round 12
// baseline (speedup 1.0000x reference)
#include <cuda_runtime.h>
#include <cstdint>

#define NUM_CLASSES 100000
#define FEAT_DIM    128
#define BATCH       16384
#define LOSS_WEIGHT 0.01f
#define TOTAL       (NUM_CLASSES * FEAT_DIM)      // 12,800,000

// ---- K1: histogram blocks + zerofill blocks ----
#define HIST_THREADS 256
#define HIST_BLOCKS  (BATCH / HIST_THREADS)       // 64
// Zerofill: shifted float4 vectors over grad (= out+1, 4B-aligned):
// element e is 16B-aligned iff e ≡ 3 (mod 4); vectors cover [3, 3+4*K3_NV).
#define K3_NV ((TOTAL - 3) / 4)                   // 3,199,999
#define ZF_VPT 4
#define ZF_VPB (256 * ZF_VPT)                     // 1024 vectors/block
#define ZF_BLOCKS ((K3_NV + 1 + ZF_VPB - 1) / ZF_VPB)   // 3126

// ---- K2: scatter blocks + hit blocks ----
#define K4_WARPS   8
#define K4_SPW     4
#define SPB        (K4_WARPS * K4_SPW)            // 32 samples/block
#define K4_THREADS (K4_WARPS * 32)
#define SCATTER_BLOCKS (BATCH / SPB)              // 512
#define HIT_SPW    4
#define HIT_BLOCKS (BATCH / (K4_WARPS * HIT_SPW)) // 512

// Static scratch — zero-initialized at load; every call restores the
// zero-invariant on exactly what it touched (graph-replay safe).
__device__ float g_counts[NUM_CLASSES];
__device__ int   g_hitlist[BATCH];   // c+1, densely packed; 0 = empty slot
__device__ int   g_nhit;             // append cursor
__device__ float g_loss;             // loss accumulator

// Shared-memory label-dtype probe over a FIXED in-bounds range (odd 32-bit
// words of the first 32 int64-slots). int64 labels (<2^31) -> all zero;
// int32 -> real labels, P(all zero) ~ 1e-160.
__device__ __forceinline__ int probe_is64(const void* y, int* s_flag) {
    if (threadIdx.x < 32) {
        int odd = ((const int*)y)[2 * threadIdx.x + 1];
        unsigned b = __ballot_sync(0xFFFFFFFFu, odd != 0);
        if (threadIdx.x == 0) *s_flag = (b == 0u) ? 1 : 0;
    }
    __syncthreads();
    return *s_flag;
}

// ---------------------------------------------------------------------------
// K1: blocks [0,64): counts histogram + first-toucher hitlist.
//     blocks [64,...): branch-free zero-fill of grad (streaming float4).
// Disjoint writes (counts/hitlist vs grad) -> safe to overlap.
// ---------------------------------------------------------------------------
__global__ void __launch_bounds__(HIST_THREADS)
k1_hist_zero(const void* __restrict__ y, float* __restrict__ grad) {
    if (blockIdx.x >= HIST_BLOCKS) {
        int vbase = (blockIdx.x - HIST_BLOCKS) * ZF_VPB;
        const float4 z = make_float4(0.f, 0.f, 0.f, 0.f);
        #pragma unroll
        for (int k = 0; k < ZF_VPT; k++) {
            int j = vbase + k * 256 + threadIdx.x;
            if (j < K3_NV)
                __stcs(reinterpret_cast<float4*>(grad + 4 * j + 3), z);
        }
        if (vbase + threadIdx.x == K3_NV) {   // head (elems 0..2) + tail
            grad[0] = 0.0f; grad[1] = 0.0f; grad[2] = 0.0f;
            grad[TOTAL - 1] = 0.0f;
        }
        return;
    }

    __shared__ int s_is64;
    int is64 = probe_is64(y, &s_is64);

    int i = blockIdx.x * HIST_THREADS + threadIdx.x;
    int c = is64 ? (int)((const long long*)y)[i] : ((const int*)y)[i];

    float old = atomicAdd(&g_counts[c], 1.0f);
    if (old == 0.0f) {
        int pos = atomicAdd(&g_nhit, 1);
        g_hitlist[pos] = c + 1;
    }
}

// ---------------------------------------------------------------------------
// K2: blocks [0,512): per-sample RED(-feat*inv) into grad + fused loss.
//     blocks [512,1024): per-hit-class RED(+ratio*centers) into grad.
// Both contributions are commutative adds into zeroed grad -> no ordering.
// counts are final (K1 boundary) and L2-hot.
// ---------------------------------------------------------------------------
__global__ void __launch_bounds__(K4_THREADS)
k2_scatter(const void* __restrict__ y,
           const float* __restrict__ feat,
           const float* __restrict__ centers,
           float* __restrict__ grad) {
    int wid  = threadIdx.x >> 5;
    int lane = threadIdx.x & 31;

    if (blockIdx.x >= SCATTER_BLOCKS) {
        // ---- hit path: grad[c,:] += ratio * centers[c,:] ----
        int slotBase = ((blockIdx.x - SCATTER_BLOCKS) * K4_WARPS + wid) * HIT_SPW;

        int e[HIT_SPW];
        #pragma unroll
        for (int s = 0; s < HIT_SPW; s++)
            e[s] = g_hitlist[slotBase + s];
        if ((e[0] | e[1] | e[2] | e[3]) == 0) return;   // dense list tail

        int c[HIT_SPW];
        #pragma unroll
        for (int s = 0; s < HIT_SPW; s++)
            c[s] = (e[s] > 0) ? (e[s] - 1) : 0;

        float cnt[HIT_SPW];
        #pragma unroll
        for (int s = 0; s < HIT_SPW; s++)
            cnt[s] = g_counts[c[s]];

        float4 ce[HIT_SPW];
        #pragma unroll
        for (int s = 0; s < HIT_SPW; s++)
            ce[s] = __ldg(reinterpret_cast<const float4*>(
                              centers + c[s] * FEAT_DIM) + lane);

        #pragma unroll
        for (int s = 0; s < HIT_SPW; s++) {
            if (e[s] > 0) {
                float r = cnt[s] / (1.0f + cnt[s]);
                float* g = grad + c[s] * FEAT_DIM + lane * 4;
                asm volatile("red.global.add.f32 [%0], %1;" :: "l"(g),     "f"(r * ce[s].x) : "memory");
                asm volatile("red.global.add.f32 [%0], %1;" :: "l"(g + 1), "f"(r * ce[s].y) : "memory");
                asm volatile("red.global.add.f32 [%0], %1;" :: "l"(g + 2), "f"(r * ce[s].z) : "memory");
                asm volatile("red.global.add.f32 [%0], %1;" :: "l"(g + 3), "f"(r * ce[s].w) : "memory");
            }
        }
        if (lane == 0) {
            #pragma unroll
            for (int s = 0; s < HIT_SPW; s++)
                if (e[s] > 0) g_hitlist[slotBase + s] = 0;   // self-reset
        }
        return;
    }

    // ---- sample path: grad[y_i,:] -= feat[i,:]/(1+cnt); loss ----
    __shared__ int s_is64;
    int is64 = probe_is64(y, &s_is64);

    int base = blockIdx.x * SPB + wid * K4_SPW;
    int c[K4_SPW];
    if (!is64) {
        int4 L = reinterpret_cast<const int4*>((const int*)y + base)[0];
        c[0] = L.x; c[1] = L.y; c[2] = L.z; c[3] = L.w;
    } else {
        const longlong2* y2 = reinterpret_cast<const longlong2*>(y);
        longlong2 a = y2[base / 2], b = y2[base / 2 + 1];
        c[0] = (int)a.x; c[1] = (int)a.y; c[2] = (int)b.x; c[3] = (int)b.y;
    }

    float inv[K4_SPW];
    #pragma unroll
    for (int s = 0; s < K4_SPW; s++)
        inv[s] = 1.0f / (1.0f + g_counts[c[s]]);

    float4 f4[K4_SPW], e4[K4_SPW];
    #pragma unroll
    for (int s = 0; s < K4_SPW; s++)
        f4[s] = reinterpret_cast<const float4*>(feat + (base + s) * FEAT_DIM)[lane];
    #pragma unroll
    for (int s = 0; s < K4_SPW; s++)
        e4[s] = __ldg(reinterpret_cast<const float4*>(
                          centers + c[s] * FEAT_DIM) + lane);

    #pragma unroll
    for (int s = 0; s < K4_SPW; s++) {
        float* g = grad + c[s] * FEAT_DIM + lane * 4;
        asm volatile("red.global.add.f32 [%0], %1;" :: "l"(g),     "f"(-f4[s].x * inv[s]) : "memory");
        asm volatile("red.global.add.f32 [%0], %1;" :: "l"(g + 1), "f"(-f4[s].y * inv[s]) : "memory");
        asm volatile("red.global.add.f32 [%0], %1;" :: "l"(g + 2), "f"(-f4[s].z * inv[s]) : "memory");
        asm volatile("red.global.add.f32 [%0], %1;" :: "l"(g + 3), "f"(-f4[s].w * inv[s]) : "memory");
    }

    float v = 0.0f;
    #pragma unroll
    for (int s = 0; s < K4_SPW; s++) {
        float d;
        d = f4[s].x - e4[s].x; v += d * d;
        d = f4[s].y - e4[s].y; v += d * d;
        d = f4[s].z - e4[s].z; v += d * d;
        d = f4[s].w - e4[s].w; v += d * d;
    }
    #pragma unroll
    for (int o = 16; o > 0; o >>= 1)
        v += __shfl_down_sync(0xFFFFFFFFu, v, o);

    __shared__ float s_part[K4_WARPS];
    if (lane == 0) s_part[wid] = v;
    __syncthreads();
    if (threadIdx.x == 0) {
        float t = 0.0f;
        #pragma unroll
        for (int w = 0; w < K4_WARPS; w++) t += s_part[w];
        asm volatile("red.global.add.f32 [%0], %1;"
                     :: "l"(&g_loss), "f"(t) : "memory");
    }
}

// ---------------------------------------------------------------------------
// K3: finalize loss + reset scratch (counts to zero, cursors).
// ---------------------------------------------------------------------------
__global__ void __launch_bounds__(256)
k3_finish(float* __restrict__ loss_out) {
    int i = blockIdx.x * blockDim.x + threadIdx.x;
    if (i < NUM_CLASSES / 4) {
        reinterpret_cast<float4*>(g_counts)[i] =
            make_float4(0.f, 0.f, 0.f, 0.f);
    }
    if (i == 0) {
        *loss_out = LOSS_WEIGHT * 0.5f * g_loss;
        g_loss = 0.0f;
        g_nhit = 0;
    }
}

// ---------------------------------------------------------------------------
extern "C" void kernel_launch(void* const* d_in, const int* in_sizes, int n_in,
                              void* d_out, int out_size) {
    const void*  y       = d_in[0];
    const float* feat    = (const float*)d_in[1];
    const float* centers = (const float*)d_in[2];

    float* out      = (float*)d_out;
    float* loss_out = out;          // output 0: scalar loss
    float* grad     = out + 1;      // output 1: [C, D] grad (4B-aligned only!)

    // K1: histogram (64 blocks) || zero-fill grad (3126 blocks)
    k1_hist_zero<<<HIST_BLOCKS + ZF_BLOCKS, HIST_THREADS>>>(y, grad);

    // K2: sample REDs + loss (512) || hit-class REDs (512) — all commutative
    k2_scatter<<<SCATTER_BLOCKS + HIT_BLOCKS, K4_THREADS>>>(y, feat, centers, grad);

    // K3: loss write + counts/cursor reset
    k3_finish<<<(NUM_CLASSES / 4 + 255) / 256, 256>>>(loss_out);
}

// round 13
// speedup vs baseline: 1.0880x; 1.0880x over previous
#include <cuda_runtime.h>
#include <cstdint>

#define NUM_CLASSES 100000
#define FEAT_DIM    128
#define BATCH       16384
#define LOSS_WEIGHT 0.01f
#define TOTAL       (NUM_CLASSES * FEAT_DIM)      // 12,800,000

// ---- K1: histogram blocks + TMA zerofill blocks ----
#define HIST_THREADS 256
#define HIST_BLOCKS  (BATCH / HIST_THREADS)       // 64
// Zerofill covers elements [3, TOTAL-1): byte range is 16B-aligned relative
// to grad (grad = out+1 -> element 3 sits on a 16B boundary) and a multiple
// of 16 bytes. Head (0..2) and tail (TOTAL-1) are scalar-zeroed in K1.
#define ZBYTES  (4u * (unsigned)(TOTAL - 4))      // 51,199,984 = 16*3,199,999
#define CHUNK_BYTES 16384u
#define NCHUNK  ((ZBYTES + CHUNK_BYTES - 1u) / CHUNK_BYTES)   // 3125
#define CPB     8                                  // chunks per block
#define ZB_BLOCKS ((NCHUNK + CPB - 1u) / CPB)      // 391

// ---- K2: scatter ----
#define K4_WARPS   8
#define K4_SPW     4
#define SPB        (K4_WARPS * K4_SPW)            // 32 samples/block
#define K4_THREADS (K4_WARPS * 32)
#define SCATTER_BLOCKS (BATCH / SPB)              // 512

// Static scratch — zero-initialized at load; every call restores the
// zero-invariant on exactly what it touched (graph-replay safe).
__device__ float g_counts[NUM_CLASSES];
__device__ float g_loss;

// Label-dtype probe over a FIXED in-bounds range (odd 32-bit words of the
// first 32 int64-slots). int64 labels (<2^31) -> all zero; int32 -> real
// labels, P(all zero) ~ 1e-160.
__device__ __forceinline__ int probe_is64(const void* y, int* s_flag) {
    if (threadIdx.x < 32) {
        int odd = ((const int*)y)[2 * threadIdx.x + 1];
        unsigned b = __ballot_sync(0xFFFFFFFFu, odd != 0);
        if (threadIdx.x == 0) *s_flag = (b == 0u) ? 1 : 0;
    }
    __syncthreads();
    return *s_flag;
}

__device__ __forceinline__ uint32_t smem_u32(const void* p) {
    uint32_t a;
    asm("{ .reg .u64 t; cvta.to.shared.u64 t, %1; cvt.u32.u64 %0, t; }"
        : "=r"(a) : "l"(p));
    return a;
}

// ---------------------------------------------------------------------------
// K1: blocks [0,64): counts histogram (+ head/tail scalar zero).
//     blocks [64,455): TMA bulk zerofill of grad — one 16KB zeroed smem
//     buffer, thread 0 issues CPB bulk copies. Store path goes through the
//     TMA engine (LTS-cap bound), not per-thread STG issue.
// ---------------------------------------------------------------------------
__global__ void __launch_bounds__(HIST_THREADS)
k1_hist_zero(const void* __restrict__ y, float* __restrict__ grad) {
    if (blockIdx.x >= HIST_BLOCKS) {
        __shared__ __align__(16) float4 zbuf[CHUNK_BYTES / 16];  // 16KB
        #pragma unroll
        for (int k = 0; k < (int)(CHUNK_BYTES / 16 / HIST_THREADS); k++)
            zbuf[threadIdx.x + HIST_THREADS * k] =
                make_float4(0.f, 0.f, 0.f, 0.f);
        __syncthreads();
        asm volatile("fence.proxy.async.shared::cta;" ::: "memory");

        if (threadIdx.x == 0) {
            uint32_t saddr = smem_u32(zbuf);
            unsigned cbase = (blockIdx.x - HIST_BLOCKS) * CPB;
            char* dbase = (char*)(grad + 3);       // 16B-aligned
            #pragma unroll
            for (int k = 0; k < CPB; k++) {
                unsigned t = cbase + k;
                if (t < NCHUNK) {
                    unsigned off = t * CHUNK_BYTES;
                    unsigned sz  = ZBYTES - off;
                    if (sz > CHUNK_BYTES) sz = CHUNK_BYTES;
                    asm volatile(
                        "cp.async.bulk.global.shared::cta.bulk_group "
                        "[%0], [%1], %2;"
                        :: "l"(dbase + off), "r"(saddr), "r"(sz) : "memory");
                }
            }
            asm volatile("cp.async.bulk.commit_group;" ::: "memory");
            asm volatile("cp.async.bulk.wait_group 0;" ::: "memory");
        }
        return;
    }

    // ---- histogram path ----
    __shared__ int s_is64;
    int is64 = probe_is64(y, &s_is64);

    int i = blockIdx.x * HIST_THREADS + threadIdx.x;
    int c = is64 ? (int)((const long long*)y)[i] : ((const int*)y)[i];
    atomicAdd(&g_counts[c], 1.0f);

    if (blockIdx.x == 0 && threadIdx.x == 0) {
        grad[0] = 0.0f; grad[1] = 0.0f; grad[2] = 0.0f;
        grad[TOTAL - 1] = 0.0f;
    }
}

// ---------------------------------------------------------------------------
// K2: per-sample RED of (centers[c,:] - feat[i,:]) * inv_c into grad + loss.
// Summed over a class this is exactly r*ce - featsum*inv — the complete
// hit-row value. Empty rows stay zero. No featsum, no hitlist, no finalize.
// ---------------------------------------------------------------------------
__global__ void __launch_bounds__(K4_THREADS)
k2_scatter(const void* __restrict__ y,
           const float* __restrict__ feat,
           const float* __restrict__ centers,
           float* __restrict__ grad) {
    __shared__ int s_is64;
    int is64 = probe_is64(y, &s_is64);

    int wid  = threadIdx.x >> 5;
    int lane = threadIdx.x & 31;
    int base = blockIdx.x * SPB + wid * K4_SPW;

    int c[K4_SPW];
    if (!is64) {
        int4 L = reinterpret_cast<const int4*>((const int*)y + base)[0];
        c[0] = L.x; c[1] = L.y; c[2] = L.z; c[3] = L.w;
    } else {
        const longlong2* y2 = reinterpret_cast<const longlong2*>(y);
        longlong2 a = y2[base / 2], b = y2[base / 2 + 1];
        c[0] = (int)a.x; c[1] = (int)a.y; c[2] = (int)b.x; c[3] = (int)b.y;
    }

    float inv[K4_SPW];
    #pragma unroll
    for (int s = 0; s < K4_SPW; s++)
        inv[s] = 1.0f / (1.0f + g_counts[c[s]]);

    // Front-batch all 8 row loads (feat + centers).
    float4 f4[K4_SPW], e4[K4_SPW];
    #pragma unroll
    for (int s = 0; s < K4_SPW; s++)
        f4[s] = reinterpret_cast<const float4*>(feat + (base + s) * FEAT_DIM)[lane];
    #pragma unroll
    for (int s = 0; s < K4_SPW; s++)
        e4[s] = __ldg(reinterpret_cast<const float4*>(
                          centers + c[s] * FEAT_DIM) + lane);

    // grad[c,:] += (ce - f) * inv   (scalar REDs; grad rows are 4B-aligned)
    #pragma unroll
    for (int s = 0; s < K4_SPW; s++) {
        float* g = grad + c[s] * FEAT_DIM + lane * 4;
        asm volatile("red.global.add.f32 [%0], %1;" :: "l"(g),     "f"((e4[s].x - f4[s].x) * inv[s]) : "memory");
        asm volatile("red.global.add.f32 [%0], %1;" :: "l"(g + 1), "f"((e4[s].y - f4[s].y) * inv[s]) : "memory");
        asm volatile("red.global.add.f32 [%0], %1;" :: "l"(g + 2), "f"((e4[s].z - f4[s].z) * inv[s]) : "memory");
        asm volatile("red.global.add.f32 [%0], %1;" :: "l"(g + 3), "f"((e4[s].w - f4[s].w) * inv[s]) : "memory");
    }

    // fused loss
    float v = 0.0f;
    #pragma unroll
    for (int s = 0; s < K4_SPW; s++) {
        float d;
        d = f4[s].x - e4[s].x; v += d * d;
        d = f4[s].y - e4[s].y; v += d * d;
        d = f4[s].z - e4[s].z; v += d * d;
        d = f4[s].w - e4[s].w; v += d * d;
    }
    #pragma unroll
    for (int o = 16; o > 0; o >>= 1)
        v += __shfl_down_sync(0xFFFFFFFFu, v, o);

    __shared__ float s_part[K4_WARPS];
    if (lane == 0) s_part[wid] = v;
    __syncthreads();
    if (threadIdx.x == 0) {
        float t = 0.0f;
        #pragma unroll
        for (int w = 0; w < K4_WARPS; w++) t += s_part[w];
        asm volatile("red.global.add.f32 [%0], %1;"
                     :: "l"(&g_loss), "f"(t) : "memory");
    }
}

// ---------------------------------------------------------------------------
// K3: finalize loss + reset counts (zero-invariant for next replay).
// ---------------------------------------------------------------------------
__global__ void __launch_bounds__(256)
k3_finish(float* __restrict__ loss_out) {
    int i = blockIdx.x * blockDim.x + threadIdx.x;
    if (i < NUM_CLASSES / 4) {
        reinterpret_cast<float4*>(g_counts)[i] =
            make_float4(0.f, 0.f, 0.f, 0.f);
    }
    if (i == 0) {
        *loss_out = LOSS_WEIGHT * 0.5f * g_loss;
        g_loss = 0.0f;
    }
}

// ---------------------------------------------------------------------------
extern "C" void kernel_launch(void* const* d_in, const int* in_sizes, int n_in,
                              void* d_out, int out_size) {
    const void*  y       = d_in[0];
    const float* feat    = (const float*)d_in[1];
    const float* centers = (const float*)d_in[2];

    float* out      = (float*)d_out;
    float* loss_out = out;          // output 0: scalar loss
    float* grad     = out + 1;      // output 1: [C, D] grad (4B-aligned only!)

    // K1: histogram (64 blocks) || TMA bulk zerofill (391 blocks)
    k1_hist_zero<<<HIST_BLOCKS + ZB_BLOCKS, HIST_THREADS>>>(y, grad);

    // K2: per-sample (ce - f)*inv REDs + fused loss
    k2_scatter<<<SCATTER_BLOCKS, K4_THREADS>>>(y, feat, centers, grad);

    // K3: loss write + counts reset
    k3_finish<<<(NUM_CLASSES / 4 + 255) / 256, 256>>>(loss_out);
}

// round 15
// speedup vs baseline: 1.1895x; 1.0932x over previous
#include <cuda_runtime.h>
#include <cstdint>

#define NUM_CLASSES 100000
#define FEAT_DIM    128
#define BATCH       16384
#define LOSS_WEIGHT 0.01f
#define TOTAL       (NUM_CLASSES * FEAT_DIM)      // 12,800,000
#define NWORDS      ((NUM_CLASSES + 31) / 32)     // 3125 bitmap words

// ---- K1: histogram + hit-row zeroing ----
#define HIST_THREADS 256
#define HIST_BLOCKS  (BATCH / HIST_THREADS)       // 64

// ---- K2: scatter blocks + bitmap-skip zerofill blocks ----
#define K4_WARPS   8
#define K4_SPW     4
#define SPB        (K4_WARPS * K4_SPW)            // 32 samples/block
#define K4_THREADS (K4_WARPS * 32)
#define SCATTER_BLOCKS (BATCH / SPB)              // 512
// Shifted float4 vectors over grad (= out+1, 4B-aligned): element e is
// 16B-aligned iff e ≡ 3 (mod 4); vectors cover [3, 3+4*K3_NV).
#define K3_NV ((TOTAL - 3) / 4)                   // 3,199,999
#define ZF_VPT 4
#define ZF_VPB (256 * ZF_VPT)                     // 1024 vectors/block
#define ZF_BLOCKS ((K3_NV + 1 + ZF_VPB - 1) / ZF_VPB)   // 3126

// Static scratch — zero-initialized at load; every call restores the
// zero-invariant on exactly what it touched (graph-replay safe).
__device__ float    g_counts[NUM_CLASSES];
__device__ unsigned g_hitbits[NWORDS];
__device__ float    g_loss;

// Label-dtype probe over a FIXED in-bounds range (odd 32-bit words of the
// first 32 int64-slots). int64 labels (<2^31) -> all zero; int32 -> real
// labels, P(all zero) ~ 1e-160.
__device__ __forceinline__ int probe_is64(const void* y, int* s_flag) {
    if (threadIdx.x < 32) {
        int odd = ((const int*)y)[2 * threadIdx.x + 1];
        unsigned b = __ballot_sync(0xFFFFFFFFu, odd != 0);
        if (threadIdx.x == 0) *s_flag = (b == 0u) ? 1 : 0;
    }
    __syncthreads();
    return *s_flag;
}

// ---------------------------------------------------------------------------
// K1: histogram + first-toucher bitmap + cooperative zeroing of hit rows.
// ---------------------------------------------------------------------------
__global__ void __launch_bounds__(HIST_THREADS)
k1_hist(const void* __restrict__ y, float* __restrict__ grad) {
    __shared__ int s_is64;
    __shared__ int s_list[HIST_THREADS];
    __shared__ int s_n;
    if (threadIdx.x == 0) s_n = 0;
    int is64 = probe_is64(y, &s_is64);   // includes __syncthreads

    int i = blockIdx.x * HIST_THREADS + threadIdx.x;
    int c = is64 ? (int)((const long long*)y)[i] : ((const int*)y)[i];

    float old = atomicAdd(&g_counts[c], 1.0f);
    if (old == 0.0f) {
        atomicOr(&g_hitbits[c >> 5], 1u << (c & 31));
        int p = atomicAdd(&s_n, 1);
        s_list[p] = c;
    }
    __syncthreads();

    // Zero hit rows, one row per warp iteration (3 head + 31 float4 + 1).
    int wid  = threadIdx.x >> 5;
    int lane = threadIdx.x & 31;
    int n = s_n;
    for (int t = wid; t < n; t += K4_WARPS) {
        float* row = grad + s_list[t] * FEAT_DIM;
        if (lane < 31) {
            *reinterpret_cast<float4*>(row + 3 + 4 * lane) =
                make_float4(0.f, 0.f, 0.f, 0.f);
        } else {
            row[0] = 0.0f; row[1] = 0.0f; row[2] = 0.0f; row[127] = 0.0f;
        }
    }
}

// ---------------------------------------------------------------------------
// K2: blocks [0,512): per-sample RED of (centers[c,:]-feat[i,:])*inv_c into
//     grad (rows pre-zeroed by K1) + fused loss.
//     blocks [512,...): zerofill of EMPTY rows only (bitmap skip) — disjoint
//     from the REDs, so the two halves overlap freely.
// Boundary vectors have e0 & 127 == 127 (element 127 of row cA + elements
// 0..2 of row cA+1) — each side gated on its own hit bit.
// ---------------------------------------------------------------------------
__global__ void __launch_bounds__(K4_THREADS)
k2_main(const void* __restrict__ y,
        const float* __restrict__ feat,
        const float* __restrict__ centers,
        float* __restrict__ grad) {
    int wid  = threadIdx.x >> 5;
    int lane = threadIdx.x & 31;

    if (blockIdx.x >= SCATTER_BLOCKS) {
        // ---- zerofill path (empty rows only) ----
        int zb    = blockIdx.x - SCATTER_BLOCKS;
        int vbase = zb * ZF_VPB;
        // rows of this block start at 32*zb (aligned) and span <= 33 rows,
        // so a 64-bit window starting at word w0 = zb covers all shifts.
        int r0  = (4 * vbase + 3) >> 7;          // = 32*zb
        int w0  = r0 >> 5;
        int w1  = (w0 + 1 < NWORDS) ? (w0 + 1) : (NWORDS - 1);
        __shared__ unsigned long long s_win;
        if (threadIdx.x == 0)
            s_win = ((unsigned long long)g_hitbits[w1] << 32) | g_hitbits[w0];
        __syncthreads();
        unsigned long long win = s_win;
        int rbase = w0 << 5;

        const float4 z = make_float4(0.f, 0.f, 0.f, 0.f);
        #pragma unroll
        for (int k = 0; k < ZF_VPT; k++) {
            int j = vbase + k * 256 + threadIdx.x;
            if (j >= K3_NV) continue;
            int e0 = 4 * j + 3;
            int cA = e0 >> 7;
            if ((e0 & 127) != 127) {
                // vector fully inside row cA
                if (!((win >> (cA - rbase)) & 1ull))
                    __stcs(reinterpret_cast<float4*>(grad + e0), z);
            } else {
                // boundary: e0 = elem 127 of row cA; e0+1..3 = elems 0..2
                // of row cA+1
                bool hA = (win >> (cA - rbase)) & 1ull;
                bool hB = (win >> (cA + 1 - rbase)) & 1ull;
                if (!hA && !hB) {
                    __stcs(reinterpret_cast<float4*>(grad + e0), z);
                } else {
                    if (!hA) grad[e0] = 0.0f;
                    if (!hB) {
                        grad[e0 + 1] = 0.0f;
                        grad[e0 + 2] = 0.0f;
                        grad[e0 + 3] = 0.0f;
                    }
                }
            }
        }
        // head (elements 0..2, row 0) and tail (TOTAL-1, last row)
        if (zb == 0 && threadIdx.x == 0) {
            if (!(g_hitbits[0] & 1u)) {
                grad[0] = 0.0f; grad[1] = 0.0f; grad[2] = 0.0f;
            }
            if (!((g_hitbits[(NUM_CLASSES - 1) >> 5] >>
                   ((NUM_CLASSES - 1) & 31)) & 1u))
                grad[TOTAL - 1] = 0.0f;
        }
        return;
    }

    // ---- scatter path ----
    __shared__ int s_is64;
    int is64 = probe_is64(y, &s_is64);

    int base = blockIdx.x * SPB + wid * K4_SPW;
    int c[K4_SPW];
    if (!is64) {
        int4 L = reinterpret_cast<const int4*>((const int*)y + base)[0];
        c[0] = L.x; c[1] = L.y; c[2] = L.z; c[3] = L.w;
    } else {
        const longlong2* y2 = reinterpret_cast<const longlong2*>(y);
        longlong2 a = y2[base / 2], b = y2[base / 2 + 1];
        c[0] = (int)a.x; c[1] = (int)a.y; c[2] = (int)b.x; c[3] = (int)b.y;
    }

    float inv[K4_SPW];
    #pragma unroll
    for (int s = 0; s < K4_SPW; s++)
        inv[s] = 1.0f / (1.0f + g_counts[c[s]]);

    float4 f4[K4_SPW], e4[K4_SPW];
    #pragma unroll
    for (int s = 0; s < K4_SPW; s++)
        f4[s] = reinterpret_cast<const float4*>(feat + (base + s) * FEAT_DIM)[lane];
    #pragma unroll
    for (int s = 0; s < K4_SPW; s++)
        e4[s] = __ldg(reinterpret_cast<const float4*>(
                          centers + c[s] * FEAT_DIM) + lane);

    // grad[c,:] += (ce - f) * inv  — complete hit-row value when summed
    #pragma unroll
    for (int s = 0; s < K4_SPW; s++) {
        float* g = grad + c[s] * FEAT_DIM + lane * 4;
        asm volatile("red.global.add.f32 [%0], %1;" :: "l"(g),     "f"((e4[s].x - f4[s].x) * inv[s]) : "memory");
        asm volatile("red.global.add.f32 [%0], %1;" :: "l"(g + 1), "f"((e4[s].y - f4[s].y) * inv[s]) : "memory");
        asm volatile("red.global.add.f32 [%0], %1;" :: "l"(g + 2), "f"((e4[s].z - f4[s].z) * inv[s]) : "memory");
        asm volatile("red.global.add.f32 [%0], %1;" :: "l"(g + 3), "f"((e4[s].w - f4[s].w) * inv[s]) : "memory");
    }

    float v = 0.0f;
    #pragma unroll
    for (int s = 0; s < K4_SPW; s++) {
        float d;
        d = f4[s].x - e4[s].x; v += d * d;
        d = f4[s].y - e4[s].y; v += d * d;
        d = f4[s].z - e4[s].z; v += d * d;
        d = f4[s].w - e4[s].w; v += d * d;
    }
    #pragma unroll
    for (int o = 16; o > 0; o >>= 1)
        v += __shfl_down_sync(0xFFFFFFFFu, v, o);

    __shared__ float s_part[K4_WARPS];
    if (lane == 0) s_part[wid] = v;
    __syncthreads();
    if (threadIdx.x == 0) {
        float t = 0.0f;
        #pragma unroll
        for (int w = 0; w < K4_WARPS; w++) t += s_part[w];
        asm volatile("red.global.add.f32 [%0], %1;"
                     :: "l"(&g_loss), "f"(t) : "memory");
    }
}

// ---------------------------------------------------------------------------
// K3: finalize loss + reset counts/bitmap (zero-invariant for next replay).
// ---------------------------------------------------------------------------
__global__ void __launch_bounds__(256)
k3_finish(float* __restrict__ loss_out) {
    int i = blockIdx.x * blockDim.x + threadIdx.x;
    if (i < NUM_CLASSES / 4) {
        reinterpret_cast<float4*>(g_counts)[i] =
            make_float4(0.f, 0.f, 0.f, 0.f);
    }
    if (i < NWORDS) g_hitbits[i] = 0u;
    if (i == 0) {
        *loss_out = LOSS_WEIGHT * 0.5f * g_loss;
        g_loss = 0.0f;
    }
}

// ---------------------------------------------------------------------------
extern "C" void kernel_launch(void* const* d_in, const int* in_sizes, int n_in,
                              void* d_out, int out_size) {
    const void*  y       = d_in[0];
    const float* feat    = (const float*)d_in[1];
    const float* centers = (const float*)d_in[2];

    float* out      = (float*)d_out;
    float* loss_out = out;          // output 0: scalar loss
    float* grad     = out + 1;      // output 1: [C, D] grad (4B-aligned only!)

    // K1: histogram + bitmap + zero hit rows
    k1_hist<<<HIST_BLOCKS, HIST_THREADS>>>(y, grad);

    // K2: scatter REDs + loss (512 blocks) || zerofill empty rows (3126)
    k2_main<<<SCATTER_BLOCKS + ZF_BLOCKS, K4_THREADS>>>(y, feat, centers, grad);

    // K3: loss write + scratch reset
    k3_finish<<<(NUM_CLASSES / 4 + 255) / 256, 256>>>(loss_out);
}

// round 16
// speedup vs baseline: 1.2058x; 1.0137x over previous
#include <cuda_runtime.h>
#include <cstdint>

#define NUM_CLASSES 100000
#define FEAT_DIM    128
#define BATCH       16384
#define LOSS_WEIGHT 0.01f
#define TOTAL       (NUM_CLASSES * FEAT_DIM)      // 12,800,000
#define NWORDS      ((NUM_CLASSES + 31) / 32)     // 3125 bitmap words

// ---- K1: histogram + hit-row zeroing ----
#define HIST_THREADS 256
#define HIST_SPB     64                            // samples per block
#define HIST_BLOCKS  (BATCH / HIST_SPB)            // 256

// ---- K2: scatter blocks + bitmap-skip zerofill blocks ----
#define K4_WARPS   8
#define K4_SPW     4
#define SPB        (K4_WARPS * K4_SPW)            // 32 samples/block
#define K4_THREADS (K4_WARPS * 32)
#define SCATTER_BLOCKS (BATCH / SPB)              // 512
// Shifted float4 vectors over grad (= out+1, 4B-aligned): element e is
// 16B-aligned iff e ≡ 3 (mod 4); vectors cover [3, 3+4*K3_NV).
#define K3_NV ((TOTAL - 3) / 4)                   // 3,199,999
#define ZF_VPT 4
#define ZF_VPB (256 * ZF_VPT)                     // 1024 vectors/block
#define ZF_BLOCKS ((K3_NV + 1 + ZF_VPB - 1) / ZF_VPB)   // 3126

// Static scratch — zero-initialized at load; every call restores the
// zero-invariant on exactly what it touched (graph-replay safe).
__device__ float    g_counts[NUM_CLASSES];
__device__ unsigned g_hitbits[NWORDS];
__device__ float    g_loss;

// Label-dtype probe over a FIXED in-bounds range (odd 32-bit words of the
// first 32 int64-slots). int64 labels (<2^31) -> all zero; int32 -> real
// labels, P(all zero) ~ 1e-160.
__device__ __forceinline__ int probe_is64(const void* y, int* s_flag) {
    if (threadIdx.x < 32) {
        int odd = ((const int*)y)[2 * threadIdx.x + 1];
        unsigned b = __ballot_sync(0xFFFFFFFFu, odd != 0);
        if (threadIdx.x == 0) *s_flag = (b == 0u) ? 1 : 0;
    }
    __syncthreads();
    return *s_flag;
}

// ---------------------------------------------------------------------------
// K1: histogram + first-toucher bitmap + cooperative zeroing of hit rows.
// 256 blocks x 64 samples: threads 0-63 do the atomics; after sync, all
// 8 warps zero the rows THIS block first-touched (block-local correctness).
// ---------------------------------------------------------------------------
__global__ void __launch_bounds__(HIST_THREADS)
k1_hist(const void* __restrict__ y, float* __restrict__ grad) {
    __shared__ int s_is64;
    __shared__ int s_list[HIST_SPB];
    __shared__ int s_n;
    if (threadIdx.x == 0) s_n = 0;
    int is64 = probe_is64(y, &s_is64);   // includes __syncthreads

    if (threadIdx.x < HIST_SPB) {
        int i = blockIdx.x * HIST_SPB + threadIdx.x;
        int c = is64 ? (int)((const long long*)y)[i] : ((const int*)y)[i];
        float old = atomicAdd(&g_counts[c], 1.0f);
        if (old == 0.0f) {
            atomicOr(&g_hitbits[c >> 5], 1u << (c & 31));
            int p = atomicAdd(&s_n, 1);
            s_list[p] = c;
        }
    }
    __syncthreads();

    // Zero this block's hit rows, one row per warp iteration
    // (3 scalar head + 31 float4 + 1 scalar tail; row base is 4B-aligned).
    int wid  = threadIdx.x >> 5;
    int lane = threadIdx.x & 31;
    int n = s_n;
    for (int t = wid; t < n; t += K4_WARPS) {
        float* row = grad + s_list[t] * FEAT_DIM;
        if (lane < 31) {
            *reinterpret_cast<float4*>(row + 3 + 4 * lane) =
                make_float4(0.f, 0.f, 0.f, 0.f);
        } else {
            row[0] = 0.0f; row[1] = 0.0f; row[2] = 0.0f; row[127] = 0.0f;
        }
    }
}

// ---------------------------------------------------------------------------
// K2: blocks [0,512): per-sample RED of (centers[c,:]-feat[i,:])*inv_c into
//     grad (hit rows pre-zeroed by K1) + fused loss.
//     blocks [512,...): zerofill of EMPTY rows only (bitmap skip) — disjoint
//     from the REDs, so the two halves overlap freely.
// Boundary vectors have e0 & 127 == 127 (element 127 of row cA + elements
// 0..2 of row cA+1) — each side gated on its own hit bit.
// ---------------------------------------------------------------------------
__global__ void __launch_bounds__(K4_THREADS)
k2_main(const void* __restrict__ y,
        const float* __restrict__ feat,
        const float* __restrict__ centers,
        float* __restrict__ grad) {
    int wid  = threadIdx.x >> 5;
    int lane = threadIdx.x & 31;

    if (blockIdx.x >= SCATTER_BLOCKS) {
        // ---- zerofill path (empty rows only) ----
        int zb    = blockIdx.x - SCATTER_BLOCKS;
        int vbase = zb * ZF_VPB;
        // rows of this block start at 32*zb (word-aligned) and span <= 33
        // rows, so a 64-bit window at word w0 = zb covers all shifts.
        int r0  = (4 * vbase + 3) >> 7;          // = 32*zb
        int w0  = r0 >> 5;
        int w1  = (w0 + 1 < NWORDS) ? (w0 + 1) : (NWORDS - 1);
        __shared__ unsigned long long s_win;
        if (threadIdx.x == 0)
            s_win = ((unsigned long long)g_hitbits[w1] << 32) | g_hitbits[w0];
        __syncthreads();
        unsigned long long win = s_win;
        int rbase = w0 << 5;

        const float4 z = make_float4(0.f, 0.f, 0.f, 0.f);
        #pragma unroll
        for (int k = 0; k < ZF_VPT; k++) {
            int j = vbase + k * 256 + threadIdx.x;
            if (j >= K3_NV) continue;
            int e0 = 4 * j + 3;
            int cA = e0 >> 7;
            if ((e0 & 127) != 127) {
                // vector fully inside row cA
                if (!((win >> (cA - rbase)) & 1ull))
                    __stcs(reinterpret_cast<float4*>(grad + e0), z);
            } else {
                // boundary: e0 = elem 127 of row cA; e0+1..3 = elems 0..2
                // of row cA+1
                bool hA = (win >> (cA - rbase)) & 1ull;
                bool hB = (win >> (cA + 1 - rbase)) & 1ull;
                if (!hA && !hB) {
                    __stcs(reinterpret_cast<float4*>(grad + e0), z);
                } else {
                    if (!hA) grad[e0] = 0.0f;
                    if (!hB) {
                        grad[e0 + 1] = 0.0f;
                        grad[e0 + 2] = 0.0f;
                        grad[e0 + 3] = 0.0f;
                    }
                }
            }
        }
        // head (elements 0..2, row 0) and tail (TOTAL-1, last row)
        if (zb == 0 && threadIdx.x == 0) {
            if (!(g_hitbits[0] & 1u)) {
                grad[0] = 0.0f; grad[1] = 0.0f; grad[2] = 0.0f;
            }
            if (!((g_hitbits[(NUM_CLASSES - 1) >> 5] >>
                   ((NUM_CLASSES - 1) & 31)) & 1u))
                grad[TOTAL - 1] = 0.0f;
        }
        return;
    }

    // ---- scatter path ----
    __shared__ int s_is64;
    int is64 = probe_is64(y, &s_is64);

    int base = blockIdx.x * SPB + wid * K4_SPW;
    int c[K4_SPW];
    if (!is64) {
        int4 L = reinterpret_cast<const int4*>((const int*)y + base)[0];
        c[0] = L.x; c[1] = L.y; c[2] = L.z; c[3] = L.w;
    } else {
        const longlong2* y2 = reinterpret_cast<const longlong2*>(y);
        longlong2 a = y2[base / 2], b = y2[base / 2 + 1];
        c[0] = (int)a.x; c[1] = (int)a.y; c[2] = (int)b.x; c[3] = (int)b.y;
    }

    float inv[K4_SPW];
    #pragma unroll
    for (int s = 0; s < K4_SPW; s++)
        inv[s] = 1.0f / (1.0f + g_counts[c[s]]);

    float4 f4[K4_SPW], e4[K4_SPW];
    #pragma unroll
    for (int s = 0; s < K4_SPW; s++)
        f4[s] = reinterpret_cast<const float4*>(feat + (base + s) * FEAT_DIM)[lane];
    #pragma unroll
    for (int s = 0; s < K4_SPW; s++)
        e4[s] = __ldg(reinterpret_cast<const float4*>(
                          centers + c[s] * FEAT_DIM) + lane);

    // grad[c,:] += (ce - f) * inv  — complete hit-row value when summed
    #pragma unroll
    for (int s = 0; s < K4_SPW; s++) {
        float* g = grad + c[s] * FEAT_DIM + lane * 4;
        asm volatile("red.global.add.f32 [%0], %1;" :: "l"(g),     "f"((e4[s].x - f4[s].x) * inv[s]) : "memory");
        asm volatile("red.global.add.f32 [%0], %1;" :: "l"(g + 1), "f"((e4[s].y - f4[s].y) * inv[s]) : "memory");
        asm volatile("red.global.add.f32 [%0], %1;" :: "l"(g + 2), "f"((e4[s].z - f4[s].z) * inv[s]) : "memory");
        asm volatile("red.global.add.f32 [%0], %1;" :: "l"(g + 3), "f"((e4[s].w - f4[s].w) * inv[s]) : "memory");
    }

    float v = 0.0f;
    #pragma unroll
    for (int s = 0; s < K4_SPW; s++) {
        float d;
        d = f4[s].x - e4[s].x; v += d * d;
        d = f4[s].y - e4[s].y; v += d * d;
        d = f4[s].z - e4[s].z; v += d * d;
        d = f4[s].w - e4[s].w; v += d * d;
    }
    #pragma unroll
    for (int o = 16; o > 0; o >>= 1)
        v += __shfl_down_sync(0xFFFFFFFFu, v, o);

    __shared__ float s_part[K4_WARPS];
    if (lane == 0) s_part[wid] = v;
    __syncthreads();
    if (threadIdx.x == 0) {
        float t = 0.0f;
        #pragma unroll
        for (int w = 0; w < K4_WARPS; w++) t += s_part[w];
        asm volatile("red.global.add.f32 [%0], %1;"
                     :: "l"(&g_loss), "f"(t) : "memory");
    }
}

// ---------------------------------------------------------------------------
// K3: finalize loss + reset counts/bitmap (zero-invariant for next replay).
// ---------------------------------------------------------------------------
__global__ void __launch_bounds__(256)
k3_finish(float* __restrict__ loss_out) {
    int i = blockIdx.x * blockDim.x + threadIdx.x;
    if (i < NUM_CLASSES / 4) {
        reinterpret_cast<float4*>(g_counts)[i] =
            make_float4(0.f, 0.f, 0.f, 0.f);
    }
    if (i < NWORDS) g_hitbits[i] = 0u;
    if (i == 0) {
        *loss_out = LOSS_WEIGHT * 0.5f * g_loss;
        g_loss = 0.0f;
    }
}

// ---------------------------------------------------------------------------
extern "C" void kernel_launch(void* const* d_in, const int* in_sizes, int n_in,
                              void* d_out, int out_size) {
    const void*  y       = d_in[0];
    const float* feat    = (const float*)d_in[1];
    const float* centers = (const float*)d_in[2];

    float* out      = (float*)d_out;
    float* loss_out = out;          // output 0: scalar loss
    float* grad     = out + 1;      // output 1: [C, D] grad (4B-aligned only!)

    // K1: histogram + bitmap + zero hit rows (256 blocks)
    k1_hist<<<HIST_BLOCKS, HIST_THREADS>>>(y, grad);

    // K2: scatter REDs + loss (512 blocks) || zerofill empty rows (3126)
    k2_main<<<SCATTER_BLOCKS + ZF_BLOCKS, K4_THREADS>>>(y, feat, centers, grad);

    // K3: loss write + scratch reset
    k3_finish<<<(NUM_CLASSES / 4 + 255) / 256, 256>>>(loss_out);
}

// round 17
// speedup vs baseline: 1.2076x; 1.0015x over previous
#include <cuda_runtime.h>
#include <cstdint>

#define NUM_CLASSES 100000
#define FEAT_DIM    128
#define BATCH       16384
#define LOSS_WEIGHT 0.01f
#define TOTAL       (NUM_CLASSES * FEAT_DIM)      // 12,800,000
#define NWORDS      ((NUM_CLASSES + 31) / 32)     // 3125 bitmap words

// ---- K1: histogram + hit-row zeroing ----
#define HIST_THREADS 256
#define HIST_SPB     32                            // samples per block
#define HIST_BLOCKS  (BATCH / HIST_SPB)            // 512

// ---- K2: scatter blocks + bitmap-skip zerofill blocks ----
#define K4_WARPS   8
#define K4_SPW     4
#define SPB        (K4_WARPS * K4_SPW)            // 32 samples/block
#define K4_THREADS (K4_WARPS * 32)
#define SCATTER_BLOCKS (BATCH / SPB)              // 512
// Shifted float4 vectors over grad (= out+1, 4B-aligned): element e is
// 16B-aligned iff e ≡ 3 (mod 4); vectors cover [3, 3+4*K3_NV).
#define K3_NV ((TOTAL - 3) / 4)                   // 3,199,999
#define ZF_VPT 4
#define ZF_VPB (256 * ZF_VPT)                     // 1024 vectors/block
#define ZF_BLOCKS ((K3_NV + 1 + ZF_VPB - 1) / ZF_VPB)   // 3126

// Static scratch — zero-initialized at load; every call restores the
// zero-invariant on exactly what it touched (graph-replay safe).
__device__ float    g_counts[NUM_CLASSES];
__device__ unsigned g_hitbits[NWORDS];
__device__ float    g_loss;

// Label-dtype probe over a FIXED in-bounds range (odd 32-bit words of the
// first 32 int64-slots). int64 labels (<2^31) -> all zero; int32 -> real
// labels, P(all zero) ~ 1e-160.
__device__ __forceinline__ int probe_is64(const void* y, int* s_flag) {
    if (threadIdx.x < 32) {
        int odd = ((const int*)y)[2 * threadIdx.x + 1];
        unsigned b = __ballot_sync(0xFFFFFFFFu, odd != 0);
        if (threadIdx.x == 0) *s_flag = (b == 0u) ? 1 : 0;
    }
    __syncthreads();
    return *s_flag;
}

// ---------------------------------------------------------------------------
// K1: histogram + first-toucher bitmap + cooperative zeroing of hit rows.
// 512 blocks x 32 samples: warp 0 does the atomics (one ~320cyc wave);
// after sync, all 8 warps zero the rows THIS block first-touched
// (block-local correctness). Head/tail odd elements zeroed here too.
// ---------------------------------------------------------------------------
__global__ void __launch_bounds__(HIST_THREADS)
k1_hist(const void* __restrict__ y, float* __restrict__ grad) {
    __shared__ int s_is64;
    __shared__ int s_list[HIST_SPB];
    __shared__ int s_n;
    if (threadIdx.x == 0) s_n = 0;
    int is64 = probe_is64(y, &s_is64);   // includes __syncthreads

    if (threadIdx.x < HIST_SPB) {
        int i = blockIdx.x * HIST_SPB + threadIdx.x;
        int c = is64 ? (int)((const long long*)y)[i] : ((const int*)y)[i];
        float old = atomicAdd(&g_counts[c], 1.0f);
        if (old == 0.0f) {
            int p = atomicAdd(&s_n, 1);
            s_list[p] = c;
            atomicOr(&g_hitbits[c >> 5], 1u << (c & 31));
        }
    }
    __syncthreads();

    // Zero this block's hit rows, one row per warp iteration
    // (3 scalar head + 31 float4 + 1 scalar tail; row base is 4B-aligned).
    int wid  = threadIdx.x >> 5;
    int lane = threadIdx.x & 31;
    int n = s_n;
    for (int t = wid; t < n; t += K4_WARPS) {
        float* row = grad + s_list[t] * FEAT_DIM;
        if (lane < 31) {
            *reinterpret_cast<float4*>(row + 3 + 4 * lane) =
                make_float4(0.f, 0.f, 0.f, 0.f);
        } else {
            row[0] = 0.0f; row[1] = 0.0f; row[2] = 0.0f; row[127] = 0.0f;
        }
    }

    // head (elements 0..2 of row 0) and tail (element 127 of last row):
    // unconditional zero here is safe — if those rows are hit, the zero
    // happens in THIS kernel (before any K2 RED), and the row-zero loop
    // above may also write them (same value, same kernel, no ordering need).
    if (blockIdx.x == 0 && threadIdx.x == 0) {
        grad[0] = 0.0f; grad[1] = 0.0f; grad[2] = 0.0f;
        grad[TOTAL - 1] = 0.0f;
    }
}

// ---------------------------------------------------------------------------
// K2: blocks [0,512): per-sample RED of (centers[c,:]-feat[i,:])*inv_c into
//     grad (hit rows pre-zeroed by K1) + fused loss.
//     blocks [512,...): zerofill of EMPTY rows only (bitmap skip) — disjoint
//     from the REDs, so the two halves overlap freely.
// Boundary vectors have e0 & 127 == 127 (element 127 of row cA + elements
// 0..2 of row cA+1) — each side gated on its own hit bit.
// ---------------------------------------------------------------------------
__global__ void __launch_bounds__(K4_THREADS)
k2_main(const void* __restrict__ y,
        const float* __restrict__ feat,
        const float* __restrict__ centers,
        float* __restrict__ grad) {
    int wid  = threadIdx.x >> 5;
    int lane = threadIdx.x & 31;

    if (blockIdx.x >= SCATTER_BLOCKS) {
        // ---- zerofill path (empty rows only) ----
        int zb    = blockIdx.x - SCATTER_BLOCKS;
        int vbase = zb * ZF_VPB;
        // rows of this block start at 32*zb (word-aligned) and span <= 33
        // rows, so a 64-bit window at word w0 = zb covers all shifts.
        int r0  = (4 * vbase + 3) >> 7;          // = 32*zb
        int w0  = r0 >> 5;
        int w1  = (w0 + 1 < NWORDS) ? (w0 + 1) : (NWORDS - 1);
        __shared__ unsigned long long s_win;
        if (threadIdx.x == 0)
            s_win = ((unsigned long long)g_hitbits[w1] << 32) | g_hitbits[w0];
        __syncthreads();
        unsigned long long win = s_win;
        int rbase = w0 << 5;

        const float4 z = make_float4(0.f, 0.f, 0.f, 0.f);
        #pragma unroll
        for (int k = 0; k < ZF_VPT; k++) {
            int j = vbase + k * 256 + threadIdx.x;
            if (j >= K3_NV) continue;
            int e0 = 4 * j + 3;
            int cA = e0 >> 7;
            if ((e0 & 127) != 127) {
                // vector fully inside row cA
                if (!((win >> (cA - rbase)) & 1ull))
                    __stcs(reinterpret_cast<float4*>(grad + e0), z);
            } else {
                // boundary: e0 = elem 127 of row cA; e0+1..3 = elems 0..2
                // of row cA+1
                bool hA = (win >> (cA - rbase)) & 1ull;
                bool hB = (win >> (cA + 1 - rbase)) & 1ull;
                if (!hA && !hB) {
                    __stcs(reinterpret_cast<float4*>(grad + e0), z);
                } else {
                    if (!hA) grad[e0] = 0.0f;
                    if (!hB) {
                        grad[e0 + 1] = 0.0f;
                        grad[e0 + 2] = 0.0f;
                        grad[e0 + 3] = 0.0f;
                    }
                }
            }
        }
        return;
    }

    // ---- scatter path ----
    __shared__ int s_is64;
    int is64 = probe_is64(y, &s_is64);

    int base = blockIdx.x * SPB + wid * K4_SPW;
    int c[K4_SPW];
    if (!is64) {
        int4 L = reinterpret_cast<const int4*>((const int*)y + base)[0];
        c[0] = L.x; c[1] = L.y; c[2] = L.z; c[3] = L.w;
    } else {
        const longlong2* y2 = reinterpret_cast<const longlong2*>(y);
        longlong2 a = y2[base / 2], b = y2[base / 2 + 1];
        c[0] = (int)a.x; c[1] = (int)a.y; c[2] = (int)b.x; c[3] = (int)b.y;
    }

    float inv[K4_SPW];
    #pragma unroll
    for (int s = 0; s < K4_SPW; s++)
        inv[s] = 1.0f / (1.0f + g_counts[c[s]]);

    float4 f4[K4_SPW], e4[K4_SPW];
    #pragma unroll
    for (int s = 0; s < K4_SPW; s++)
        f4[s] = reinterpret_cast<const float4*>(feat + (base + s) * FEAT_DIM)[lane];
    #pragma unroll
    for (int s = 0; s < K4_SPW; s++)
        e4[s] = __ldg(reinterpret_cast<const float4*>(
                          centers + c[s] * FEAT_DIM) + lane);

    // grad[c,:] += (ce - f) * inv  — complete hit-row value when summed
    #pragma unroll
    for (int s = 0; s < K4_SPW; s++) {
        float* g = grad + c[s] * FEAT_DIM + lane * 4;
        asm volatile("red.global.add.f32 [%0], %1;" :: "l"(g),     "f"((e4[s].x - f4[s].x) * inv[s]) : "memory");
        asm volatile("red.global.add.f32 [%0], %1;" :: "l"(g + 1), "f"((e4[s].y - f4[s].y) * inv[s]) : "memory");
        asm volatile("red.global.add.f32 [%0], %1;" :: "l"(g + 2), "f"((e4[s].z - f4[s].z) * inv[s]) : "memory");
        asm volatile("red.global.add.f32 [%0], %1;" :: "l"(g + 3), "f"((e4[s].w - f4[s].w) * inv[s]) : "memory");
    }

    float v = 0.0f;
    #pragma unroll
    for (int s = 0; s < K4_SPW; s++) {
        float d;
        d = f4[s].x - e4[s].x; v += d * d;
        d = f4[s].y - e4[s].y; v += d * d;
        d = f4[s].z - e4[s].z; v += d * d;
        d = f4[s].w - e4[s].w; v += d * d;
    }
    #pragma unroll
    for (int o = 16; o > 0; o >>= 1)
        v += __shfl_down_sync(0xFFFFFFFFu, v, o);

    __shared__ float s_part[K4_WARPS];
    if (lane == 0) s_part[wid] = v;
    __syncthreads();
    if (threadIdx.x == 0) {
        float t = 0.0f;
        #pragma unroll
        for (int w = 0; w < K4_WARPS; w++) t += s_part[w];
        asm volatile("red.global.add.f32 [%0], %1;"
                     :: "l"(&g_loss), "f"(t) : "memory");
    }
}

// ---------------------------------------------------------------------------
// K3: finalize loss + reset counts/bitmap (zero-invariant for next replay).
// ---------------------------------------------------------------------------
__global__ void __launch_bounds__(256)
k3_finish(float* __restrict__ loss_out) {
    int i = blockIdx.x * blockDim.x + threadIdx.x;
    if (i < NUM_CLASSES / 4) {
        reinterpret_cast<float4*>(g_counts)[i] =
            make_float4(0.f, 0.f, 0.f, 0.f);
    }
    if (i < NWORDS) g_hitbits[i] = 0u;
    if (i == 0) {
        *loss_out = LOSS_WEIGHT * 0.5f * g_loss;
        g_loss = 0.0f;
    }
}

// ---------------------------------------------------------------------------
extern "C" void kernel_launch(void* const* d_in, const int* in_sizes, int n_in,
                              void* d_out, int out_size) {
    const void*  y       = d_in[0];
    const float* feat    = (const float*)d_in[1];
    const float* centers = (const float*)d_in[2];

    float* out      = (float*)d_out;
    float* loss_out = out;          // output 0: scalar loss
    float* grad     = out + 1;      // output 1: [C, D] grad (4B-aligned only!)

    // K1: histogram + bitmap + zero hit rows (512 blocks)
    k1_hist<<<HIST_BLOCKS, HIST_THREADS>>>(y, grad);

    // K2: scatter REDs + loss (512 blocks) || zerofill empty rows (3126)
    k2_main<<<SCATTER_BLOCKS + ZF_BLOCKS, K4_THREADS>>>(y, feat, centers, grad);

    // K3: loss write + scratch reset
    k3_finish<<<(NUM_CLASSES / 4 + 255) / 256, 256>>>(loss_out);
}